// round 5
// baseline (speedup 1.0000x reference)
#include <cuda_runtime.h>
#include <cuda_bf16.h>
#include <mma.h>
#include <math.h>
#include <stdint.h>

using namespace nvcuda;

#define B_ 8
#define H_ 128
#define W_ 256
#define C_ 64
#define F_ 64
#define NPIX (B_*H_*W_)

// Scratch (allocation-free rule: __device__ globals). q/k/v as hi/lo bf16 splits.
__device__ __align__(128) __nv_bfloat16 g_qh[(size_t)NPIX * F_];
__device__ __align__(128) __nv_bfloat16 g_ql[(size_t)NPIX * F_];
__device__ __align__(128) __nv_bfloat16 g_kh[(size_t)NPIX * F_];
__device__ __align__(128) __nv_bfloat16 g_kl[(size_t)NPIX * F_];
__device__ __align__(128) __nv_bfloat16 g_vh[(size_t)NPIX * F_];
__device__ __align__(128) __nv_bfloat16 g_vl[(size_t)NPIX * F_];
// Pre-transposed, hi/lo-split weights: [tap][n=192][c=64], n = (q f | k f | v f)
__device__ __align__(128) __nv_bfloat16 g_wt_hi[9 * 192 * 64];
__device__ __align__(128) __nv_bfloat16 g_wt_lo[9 * 192 * 64];

// ---------------------------------------------------------------------------
// Weight prep: transpose + hi/lo bf16 split. Wt[tap][n][c], n = q|k|v x f.
// ---------------------------------------------------------------------------
__global__ void prep_w_kernel(const float* __restrict__ Wq,
                              const float* __restrict__ Wk,
                              const float* __restrict__ Wv)
{
    int idx = blockIdx.x * 256 + threadIdx.x;
    if (idx >= 9 * 192 * 64) return;
    int tap = idx / 12288;
    int r   = idx % 12288;
    int n   = r >> 6;
    int c   = r & 63;
    const float* src = (n < 64) ? Wq : (n < 128) ? Wk : Wv;
    float v = src[tap * 4096 + c * 64 + (n & 63)];
    __nv_bfloat16 h = __float2bfloat16_rn(v);
    g_wt_hi[idx] = h;
    g_wt_lo[idx] = __float2bfloat16_rn(v - __bfloat162float(h));
}

// ---------------------------------------------------------------------------
// wmma bf16 conv: implicit GEMM, M=128 pixels, N=192 (q|k|v), K=576.
// Split-bf16: D += Ah*Bh + Ah*Bl + Al*Bh (fp32 accum in fragments).
// grid (W_/128, B_*H_), 256 threads = 8 warps (4m x 2n).
// Epilogue stores q/k/v as hi/lo bf16 pairs.
// ---------------------------------------------------------------------------
#define A_LDM 72
#define B_LDM 72
#define SM_A_HI 0
#define SM_A_LO (SM_A_HI + 132*A_LDM*2)          // 19008
#define SM_B_HI (SM_A_LO + 132*A_LDM*2)          // 38016
#define SM_B_LO (SM_B_HI + 192*B_LDM*2)          // 65664
#define CONV_SMEM (SM_B_LO + 192*B_LDM*2)        // 93312 B
#define BIAS_LDM 200
#define EPI_LDM 200                               // 64 x 200 fp32 staging (51200 B)

__global__ __launch_bounds__(256, 1)
void conv_qkv_wmma_kernel(const float* __restrict__ X,
                          const float* __restrict__ bq,
                          const float* __restrict__ bk,
                          const float* __restrict__ bv)
{
    extern __shared__ char sm[];
    __nv_bfloat16* A_hi = reinterpret_cast<__nv_bfloat16*>(sm + SM_A_HI);
    __nv_bfloat16* A_lo = reinterpret_cast<__nv_bfloat16*>(sm + SM_A_LO);
    __nv_bfloat16* B_hi = reinterpret_cast<__nv_bfloat16*>(sm + SM_B_HI);
    __nv_bfloat16* B_lo = reinterpret_cast<__nv_bfloat16*>(sm + SM_B_LO);
    float* biasT = reinterpret_cast<float*>(sm + SM_B_HI);   // transient

    const int t   = threadIdx.x;
    const int wid = t >> 5;
    const int warp_m = wid >> 1;
    const int warp_n = wid & 1;
    const int bh  = blockIdx.y;
    const int b   = bh / H_;
    const int h   = bh % H_;
    const int w0  = blockIdx.x * 128;

    // ---- replicated bias tile -> init accumulators ----
    for (int idx = t; idx < 16 * 192; idx += 256) {
        int row = idx / 192, col = idx % 192;
        float bvv = (col < 64) ? bq[col] : (col < 128) ? bk[col - 64] : bv[col - 128];
        biasT[row * BIAS_LDM + col] = bvv;
    }
    __syncthreads();

    wmma::fragment<wmma::accumulator, 16, 16, 16, float> acc[2][6];
    #pragma unroll
    for (int i = 0; i < 2; i++)
        #pragma unroll
        for (int j = 0; j < 6; j++)
            wmma::load_matrix_sync(acc[i][j], biasT + warp_n * 96 + j * 16,
                                   BIAS_LDM, wmma::mem_row_major);

    #pragma unroll 1
    for (int kh = 0; kh < 3; kh++) {
        __syncthreads();

        const int hh = h + (kh - 1) * 2;
        const bool hok = (hh >= 0) && (hh < H_);
        const float* xrow = X + ((size_t)(b * H_ + hh) * W_) * C_;

        for (int idx = t; idx < 132 * 16; idx += 256) {
            int r  = idx >> 4;
            int c4 = idx & 15;
            int ww = w0 + r - 2;
            float4 xv = make_float4(0.f, 0.f, 0.f, 0.f);
            if (hok && (unsigned)ww < (unsigned)W_)
                xv = *reinterpret_cast<const float4*>(xrow + (size_t)ww * C_ + c4 * 4);
            __nv_bfloat162 h01 = __floats2bfloat162_rn(xv.x, xv.y);
            __nv_bfloat162 h23 = __floats2bfloat162_rn(xv.z, xv.w);
            __nv_bfloat162 l01 = __floats2bfloat162_rn(
                xv.x - __bfloat162float(__low2bfloat16(h01)),
                xv.y - __bfloat162float(__high2bfloat16(h01)));
            __nv_bfloat162 l23 = __floats2bfloat162_rn(
                xv.z - __bfloat162float(__low2bfloat16(h23)),
                xv.w - __bfloat162float(__high2bfloat16(h23)));
            uint2 hv, lv;
            hv.x = *reinterpret_cast<uint32_t*>(&h01);
            hv.y = *reinterpret_cast<uint32_t*>(&h23);
            lv.x = *reinterpret_cast<uint32_t*>(&l01);
            lv.y = *reinterpret_cast<uint32_t*>(&l23);
            *reinterpret_cast<uint2*>(A_hi + r * A_LDM + c4 * 4) = hv;
            *reinterpret_cast<uint2*>(A_lo + r * A_LDM + c4 * 4) = lv;
        }

        #pragma unroll 1
        for (int kw = 0; kw < 3; kw++) {
            if (kw) __syncthreads();

            const int tap = kh * 3 + kw;
            const __nv_bfloat16* wh = g_wt_hi + tap * 12288;
            const __nv_bfloat16* wl = g_wt_lo + tap * 12288;
            #pragma unroll
            for (int i = 0; i < 6; i++) {
                int idx = t + i * 256;
                int n   = idx >> 3;
                int c8  = idx & 7;
                float4 vh = *reinterpret_cast<const float4*>(wh + n * 64 + c8 * 8);
                float4 vl = *reinterpret_cast<const float4*>(wl + n * 64 + c8 * 8);
                *reinterpret_cast<float4*>(B_hi + n * B_LDM + c8 * 8) = vh;
                *reinterpret_cast<float4*>(B_lo + n * B_LDM + c8 * 8) = vl;
            }
            __syncthreads();

            const int rbase = warp_m * 32 + kw * 2;
            #pragma unroll
            for (int ks = 0; ks < 4; ks++) {
                const int c0 = ks * 16;
                wmma::fragment<wmma::matrix_a, 16, 16, 16, __nv_bfloat16, wmma::row_major> ah[2], al[2];
                #pragma unroll
                for (int i = 0; i < 2; i++) {
                    wmma::load_matrix_sync(ah[i], A_hi + (rbase + i * 16) * A_LDM + c0, A_LDM);
                    wmma::load_matrix_sync(al[i], A_lo + (rbase + i * 16) * A_LDM + c0, A_LDM);
                }
                #pragma unroll
                for (int j = 0; j < 6; j++) {
                    wmma::fragment<wmma::matrix_b, 16, 16, 16, __nv_bfloat16, wmma::col_major> bhf, blf;
                    const int n0 = warp_n * 96 + j * 16;
                    wmma::load_matrix_sync(bhf, B_hi + n0 * B_LDM + c0, B_LDM);
                    wmma::load_matrix_sync(blf, B_lo + n0 * B_LDM + c0, B_LDM);
                    #pragma unroll
                    for (int i = 0; i < 2; i++) {
                        wmma::mma_sync(acc[i][j], ah[i], bhf, acc[i][j]);
                        wmma::mma_sync(acc[i][j], ah[i], blf, acc[i][j]);
                        wmma::mma_sync(acc[i][j], al[i], bhf, acc[i][j]);
                    }
                }
            }
        }
    }

    // ---- epilogue: stage fp32 -> split to hi/lo bf16 -> gmem ----
    float* epi = reinterpret_cast<float*>(sm);
    #pragma unroll 1
    for (int half = 0; half < 2; half++) {
        __syncthreads();   // half 0: MMAs done reading A/B; half 1: prior reads done
        #pragma unroll
        for (int j = 0; j < 6; j++)
            wmma::store_matrix_sync(epi + (warp_m * 16) * EPI_LDM + warp_n * 96 + j * 16,
                                    acc[half][j], EPI_LDM, wmma::mem_row_major);
        __syncthreads();
        #pragma unroll 4
        for (int it = 0; it < 12; it++) {
            int g  = t + it * 256;          // 0..3071 granules of float4
            int s  = g / 48;
            int c4 = g % 48;
            int m  = (s >> 4) * 32 + half * 16 + (s & 15);
            size_t pix = (size_t)bh * W_ + w0 + m;
            float4 v4 = *reinterpret_cast<const float4*>(epi + s * EPI_LDM + c4 * 4);
            __nv_bfloat162 h01 = __floats2bfloat162_rn(v4.x, v4.y);
            __nv_bfloat162 h23 = __floats2bfloat162_rn(v4.z, v4.w);
            __nv_bfloat162 l01 = __floats2bfloat162_rn(
                v4.x - __bfloat162float(__low2bfloat16(h01)),
                v4.y - __bfloat162float(__high2bfloat16(h01)));
            __nv_bfloat162 l23 = __floats2bfloat162_rn(
                v4.z - __bfloat162float(__low2bfloat16(h23)),
                v4.w - __bfloat162float(__high2bfloat16(h23)));
            int col = c4 * 4;
            __nv_bfloat16 *dh, *dl;
            if (col < 64)       { dh = g_qh; dl = g_ql; }
            else if (col < 128) { dh = g_kh; dl = g_kl; }
            else                { dh = g_vh; dl = g_vl; }
            uint2 hv, lv;
            hv.x = *reinterpret_cast<uint32_t*>(&h01);
            hv.y = *reinterpret_cast<uint32_t*>(&h23);
            lv.x = *reinterpret_cast<uint32_t*>(&l01);
            lv.y = *reinterpret_cast<uint32_t*>(&l23);
            *reinterpret_cast<uint2*>(dh + pix * 64 + (col & 63)) = hv;
            *reinterpret_cast<uint2*>(dl + pix * 64 + (col & 63)) = lv;
        }
    }
}

// ---------------------------------------------------------------------------
// wmma attention: per block = 32 q-rows of one (b,h). Full S row-block
// (32x256 fp32) in smem -> plain softmax (no online rescale) -> PV.
// All GEMM operands split-bf16 (3 MMAs). grid (8, 1024), 256 thr = 8 warps.
// ---------------------------------------------------------------------------
#define ATS_QH 0
#define ATS_QL 4608
#define ATS_KH 9216
#define ATS_KL 18432
#define ATS_S  27648                      // [32][264] fp32
#define ATS_PH 61440
#define ATS_PL 66048
#define ATS_L  70656
#define ATTN_SMEM (ATS_L + 128)           // 70784 B

__global__ __launch_bounds__(256)
void attn_wmma_kernel(float* __restrict__ out)
{
    extern __shared__ char sm[];
    __nv_bfloat16* Qh = reinterpret_cast<__nv_bfloat16*>(sm + ATS_QH);
    __nv_bfloat16* Ql = reinterpret_cast<__nv_bfloat16*>(sm + ATS_QL);
    __nv_bfloat16* Kh = reinterpret_cast<__nv_bfloat16*>(sm + ATS_KH);
    __nv_bfloat16* Kl = reinterpret_cast<__nv_bfloat16*>(sm + ATS_KL);
    float*         Ss = reinterpret_cast<float*>(sm + ATS_S);
    __nv_bfloat16* Ph = reinterpret_cast<__nv_bfloat16*>(sm + ATS_PH);
    __nv_bfloat16* Pl = reinterpret_cast<__nv_bfloat16*>(sm + ATS_PL);
    float*       Lrow = reinterpret_cast<float*>(sm + ATS_L);

    const int t  = threadIdx.x;
    const int w  = t >> 5;
    const int mi = w & 1;          // q 16-row half
    const int nj = w >> 1;         // 16-col group (of 64)
    const int bh = blockIdx.y;
    const int q0 = blockIdx.x * 32;
    const size_t base = (size_t)bh * W_ * 64;

    // ---- load Q tile (32 rows, hi/lo) ----
    {
        int row = t >> 3, c8 = t & 7;
        size_t src = base + (size_t)(q0 + row) * 64 + c8 * 8;
        *reinterpret_cast<uint4*>(Qh + row * 72 + c8 * 8) =
            *reinterpret_cast<const uint4*>(g_qh + src);
        *reinterpret_cast<uint4*>(Ql + row * 72 + c8 * 8) =
            *reinterpret_cast<const uint4*>(g_ql + src);
    }

    // ---- S phase: 4 K-tiles of 64 ----
    #pragma unroll 1
    for (int kt = 0; kt < 4; kt++) {
        __syncthreads();   // prev tile MMAs done reading Kh/Kl (and Q store visible)
        #pragma unroll
        for (int i = 0; i < 2; i++) {
            int idx = t + i * 256;
            int row = idx >> 3, c8 = idx & 7;
            size_t src = base + (size_t)(kt * 64 + row) * 64 + c8 * 8;
            *reinterpret_cast<uint4*>(Kh + row * 72 + c8 * 8) =
                *reinterpret_cast<const uint4*>(g_kh + src);
            *reinterpret_cast<uint4*>(Kl + row * 72 + c8 * 8) =
                *reinterpret_cast<const uint4*>(g_kl + src);
        }
        __syncthreads();

        wmma::fragment<wmma::accumulator, 16, 16, 16, float> sacc;
        wmma::fill_fragment(sacc, 0.f);
        #pragma unroll
        for (int ks = 0; ks < 4; ks++) {
            wmma::fragment<wmma::matrix_a, 16, 16, 16, __nv_bfloat16, wmma::row_major> qah, qal;
            wmma::fragment<wmma::matrix_b, 16, 16, 16, __nv_bfloat16, wmma::col_major> kbh, kbl;
            wmma::load_matrix_sync(qah, Qh + mi * 16 * 72 + ks * 16, 72);
            wmma::load_matrix_sync(qal, Ql + mi * 16 * 72 + ks * 16, 72);
            wmma::load_matrix_sync(kbh, Kh + nj * 16 * 72 + ks * 16, 72);
            wmma::load_matrix_sync(kbl, Kl + nj * 16 * 72 + ks * 16, 72);
            wmma::mma_sync(sacc, qah, kbh, sacc);
            wmma::mma_sync(sacc, qah, kbl, sacc);
            wmma::mma_sync(sacc, qal, kbh, sacc);
        }
        wmma::store_matrix_sync(Ss + mi * 16 * 264 + kt * 64 + nj * 16, sacc,
                                264, wmma::mem_row_major);
    }
    __syncthreads();

    // ---- softmax over full rows (exp unnormalized; 1/l folded at the end) ----
    {
        int row = t >> 3, g = t & 7;
        float* sr = Ss + row * 264 + g * 32;
        float4 r[8];
        float mx = -INFINITY;
        #pragma unroll
        for (int j = 0; j < 8; j++) {
            r[j] = reinterpret_cast<float4*>(sr)[j];
            mx = fmaxf(mx, fmaxf(fmaxf(r[j].x, r[j].y), fmaxf(r[j].z, r[j].w)));
        }
        #pragma unroll
        for (int d = 1; d < 8; d <<= 1)
            mx = fmaxf(mx, __shfl_xor_sync(0xffffffffu, mx, d));
        float sum = 0.f;
        #pragma unroll
        for (int j = 0; j < 8; j++) {
            r[j].x = __expf(r[j].x - mx);
            r[j].y = __expf(r[j].y - mx);
            r[j].z = __expf(r[j].z - mx);
            r[j].w = __expf(r[j].w - mx);
            sum += (r[j].x + r[j].y) + (r[j].z + r[j].w);
            reinterpret_cast<float4*>(sr)[j] = r[j];
        }
        #pragma unroll
        for (int d = 1; d < 8; d <<= 1)
            sum += __shfl_xor_sync(0xffffffffu, sum, d);
        if (g == 0) Lrow[row] = sum;
    }

    // ---- PV phase ----
    wmma::fragment<wmma::accumulator, 16, 16, 16, float> oacc;
    wmma::fill_fragment(oacc, 0.f);
    #pragma unroll 1
    for (int kt = 0; kt < 4; kt++) {
        __syncthreads();   // softmax done / prev MMAs done reading Kh/Ph
        #pragma unroll
        for (int i = 0; i < 2; i++) {
            int idx = t + i * 256;
            int row = idx >> 3, c8 = idx & 7;
            size_t src = base + (size_t)(kt * 64 + row) * 64 + c8 * 8;
            *reinterpret_cast<uint4*>(Kh + row * 72 + c8 * 8) =
                *reinterpret_cast<const uint4*>(g_vh + src);
            *reinterpret_cast<uint4*>(Kl + row * 72 + c8 * 8) =
                *reinterpret_cast<const uint4*>(g_vl + src);
        }
        // convert P chunk [32][64] to hi/lo bf16
        {
            int row = t >> 3, c8 = t & 7;
            const float* ps = Ss + row * 264 + kt * 64 + c8 * 8;
            float4 a = reinterpret_cast<const float4*>(ps)[0];
            float4 b = reinterpret_cast<const float4*>(ps)[1];
            __nv_bfloat162 h01 = __floats2bfloat162_rn(a.x, a.y);
            __nv_bfloat162 h23 = __floats2bfloat162_rn(a.z, a.w);
            __nv_bfloat162 h45 = __floats2bfloat162_rn(b.x, b.y);
            __nv_bfloat162 h67 = __floats2bfloat162_rn(b.z, b.w);
            __nv_bfloat162 l01 = __floats2bfloat162_rn(
                a.x - __bfloat162float(__low2bfloat16(h01)),
                a.y - __bfloat162float(__high2bfloat16(h01)));
            __nv_bfloat162 l23 = __floats2bfloat162_rn(
                a.z - __bfloat162float(__low2bfloat16(h23)),
                a.w - __bfloat162float(__high2bfloat16(h23)));
            __nv_bfloat162 l45 = __floats2bfloat162_rn(
                b.x - __bfloat162float(__low2bfloat16(h45)),
                b.y - __bfloat162float(__high2bfloat16(h45)));
            __nv_bfloat162 l67 = __floats2bfloat162_rn(
                b.z - __bfloat162float(__low2bfloat16(h67)),
                b.w - __bfloat162float(__high2bfloat16(h67)));
            uint4 hv, lv;
            hv.x = *reinterpret_cast<uint32_t*>(&h01);
            hv.y = *reinterpret_cast<uint32_t*>(&h23);
            hv.z = *reinterpret_cast<uint32_t*>(&h45);
            hv.w = *reinterpret_cast<uint32_t*>(&h67);
            lv.x = *reinterpret_cast<uint32_t*>(&l01);
            lv.y = *reinterpret_cast<uint32_t*>(&l23);
            lv.z = *reinterpret_cast<uint32_t*>(&l45);
            lv.w = *reinterpret_cast<uint32_t*>(&l67);
            *reinterpret_cast<uint4*>(Ph + row * 72 + c8 * 8) = hv;
            *reinterpret_cast<uint4*>(Pl + row * 72 + c8 * 8) = lv;
        }
        __syncthreads();

        #pragma unroll
        for (int ks = 0; ks < 4; ks++) {
            wmma::fragment<wmma::matrix_a, 16, 16, 16, __nv_bfloat16, wmma::row_major> pah, pal;
            wmma::fragment<wmma::matrix_b, 16, 16, 16, __nv_bfloat16, wmma::row_major> vbh, vbl;
            wmma::load_matrix_sync(pah, Ph + mi * 16 * 72 + ks * 16, 72);
            wmma::load_matrix_sync(pal, Pl + mi * 16 * 72 + ks * 16, 72);
            wmma::load_matrix_sync(vbh, Kh + ks * 16 * 72 + nj * 16, 72);
            wmma::load_matrix_sync(vbl, Kl + ks * 16 * 72 + nj * 16, 72);
            wmma::mma_sync(oacc, pah, vbh, oacc);
            wmma::mma_sync(oacc, pah, vbl, oacc);
            wmma::mma_sync(oacc, pal, vbh, oacc);
        }
    }

    // ---- epilogue: O to smem, scale by 1/l, store fp32 ----
    __syncthreads();
    float* Os = reinterpret_cast<float*>(sm + ATS_S);   // [32][72] fp32 reuse
    wmma::store_matrix_sync(Os + mi * 16 * 72 + nj * 16, oacc, 72, wmma::mem_row_major);
    __syncthreads();
    {
        int row = t >> 3, c8 = t & 7;
        float inv = 1.0f / Lrow[row];
        const float* orow = Os + row * 72 + c8 * 8;
        float4 a = reinterpret_cast<const float4*>(orow)[0];
        float4 b = reinterpret_cast<const float4*>(orow)[1];
        a.x *= inv; a.y *= inv; a.z *= inv; a.w *= inv;
        b.x *= inv; b.y *= inv; b.z *= inv; b.w *= inv;
        size_t dst = base + (size_t)(q0 + row) * 64 + c8 * 8;
        reinterpret_cast<float4*>(out + dst)[0] = a;
        reinterpret_cast<float4*>(out + dst)[1] = b;
    }
}

// ---------------------------------------------------------------------------
extern "C" void kernel_launch(void* const* d_in, const int* in_sizes, int n_in,
                              void* d_out, int out_size)
{
    const float* X  = (const float*)d_in[0];
    const float* Wq = (const float*)d_in[1];
    const float* bq = (const float*)d_in[2];
    const float* Wk = (const float*)d_in[3];
    const float* bk = (const float*)d_in[4];
    const float* Wv = (const float*)d_in[5];
    const float* bv = (const float*)d_in[6];
    float* out = (float*)d_out;

    cudaFuncSetAttribute(conv_qkv_wmma_kernel,
                         cudaFuncAttributeMaxDynamicSharedMemorySize, CONV_SMEM);
    cudaFuncSetAttribute(attn_wmma_kernel,
                         cudaFuncAttributeMaxDynamicSharedMemorySize, ATTN_SMEM);

    prep_w_kernel<<<(9 * 192 * 64 + 255) / 256, 256>>>(Wq, Wk, Wv);

    dim3 cgrid(W_ / 128, B_ * H_);
    conv_qkv_wmma_kernel<<<cgrid, 256, CONV_SMEM>>>(X, bq, bk, bv);

    dim3 agrid(W_ / 32, B_ * H_);
    attn_wmma_kernel<<<agrid, 256, ATTN_SMEM>>>(out);
}

// round 6
// speedup vs baseline: 1.5082x; 1.5082x over previous
#include <cuda_runtime.h>
#include <cuda_bf16.h>
#include <mma.h>
#include <math.h>
#include <stdint.h>

using namespace nvcuda;

#define B_ 8
#define H_ 128
#define W_ 256
#define C_ 64
#define F_ 64
#define NPIX (B_*H_*W_)

// Scratch (allocation-free rule: __device__ globals)
__device__ float g_q[(size_t)NPIX * F_];
__device__ float g_k[(size_t)NPIX * F_];
__device__ float g_v[(size_t)NPIX * F_];
// Pre-transposed, hi/lo-split weights: [tap][n=192][c=64], n = (q f | k f | v f)
__device__ __align__(128) __nv_bfloat16 g_wt_hi[9 * 192 * 64];
__device__ __align__(128) __nv_bfloat16 g_wt_lo[9 * 192 * 64];

// ---------------------------------------------------------------------------
// Weight prep: transpose + hi/lo bf16 split. Wt[tap][n][c], n = q|k|v x f.
// ---------------------------------------------------------------------------
__global__ void prep_w_kernel(const float* __restrict__ Wq,
                              const float* __restrict__ Wk,
                              const float* __restrict__ Wv)
{
    int idx = blockIdx.x * 256 + threadIdx.x;
    if (idx >= 9 * 192 * 64) return;
    int tap = idx / 12288;
    int r   = idx % 12288;
    int n   = r >> 6;
    int c   = r & 63;
    const float* src = (n < 64) ? Wq : (n < 128) ? Wk : Wv;
    float v = src[tap * 4096 + c * 64 + (n & 63)];
    __nv_bfloat16 h = __float2bfloat16_rn(v);
    g_wt_hi[idx] = h;
    g_wt_lo[idx] = __float2bfloat16_rn(v - __bfloat162float(h));
}

// ---------------------------------------------------------------------------
// wmma bf16 conv: implicit GEMM, M=128 pixels, N=192 (q|k|v), K=576.
// Split-bf16: D += Ah*Bh + Ah*Bl + Al*Bh (fp32 accum in fragments).
// B (weights) staged via cp.async, DOUBLE-BUFFERED across taps.
// grid (W_/128, B_*H_), 256 threads = 8 warps (4m x 2n).
// ---------------------------------------------------------------------------
#define A_LDM 72
#define B_LDM 72
#define SM_A_HI 0
#define SM_A_LO (SM_A_HI + 132*A_LDM*2)          // 19008
#define SM_B0   (SM_A_LO + 132*A_LDM*2)          // 38016
#define B_BUF_BYTES (192*B_LDM*2)                // 27648 per hi/lo plane
#define SM_BH(buf) (SM_B0 + (buf)*2*B_BUF_BYTES)
#define SM_BL(buf) (SM_BH(buf) + B_BUF_BYTES)
#define CONV_SMEM (SM_B0 + 4*B_BUF_BYTES)        // 148608 B
#define BIAS_LDM 200                              // bias tile transient in A area

__device__ __forceinline__ uint32_t smem_u32(const void* p) {
    uint32_t a;
    asm("{ .reg .u64 t; cvta.to.shared.u64 t, %1; cvt.u32.u64 %0, t; }" : "=r"(a) : "l"(p));
    return a;
}
__device__ __forceinline__ void cp16(uint32_t s, const void* g) {
    asm volatile("cp.async.cg.shared.global [%0], [%1], 16;" :: "r"(s), "l"(g));
}
__device__ __forceinline__ void issue_B(int tap, int buf, uint32_t smb, int t) {
    const __nv_bfloat16* wh = g_wt_hi + tap * 12288;
    const __nv_bfloat16* wl = g_wt_lo + tap * 12288;
    const uint32_t dh = smb + SM_BH(buf);
    const uint32_t dl = smb + SM_BL(buf);
    #pragma unroll
    for (int i = 0; i < 6; i++) {
        int idx = t + i * 256;              // 1536 chunks of 16B per plane
        int n   = idx >> 3;
        int c8  = idx & 7;
        uint32_t off = (uint32_t)(n * B_LDM + c8 * 8) * 2;
        cp16(dh + off, wh + n * 64 + c8 * 8);
        cp16(dl + off, wl + n * 64 + c8 * 8);
    }
    asm volatile("cp.async.commit_group;" ::: "memory");
}

__global__ __launch_bounds__(256, 1)
void conv_qkv_wmma_kernel(const float* __restrict__ X,
                          const float* __restrict__ bq,
                          const float* __restrict__ bk,
                          const float* __restrict__ bv)
{
    extern __shared__ char sm[];
    const uint32_t smb = smem_u32(sm);
    __nv_bfloat16* A_hi = reinterpret_cast<__nv_bfloat16*>(sm + SM_A_HI);
    __nv_bfloat16* A_lo = reinterpret_cast<__nv_bfloat16*>(sm + SM_A_LO);
    float* biasT = reinterpret_cast<float*>(sm);     // transient in A area

    const int t   = threadIdx.x;
    const int wid = t >> 5;
    const int warp_m = wid >> 1;
    const int warp_n = wid & 1;
    const int bh  = blockIdx.y;
    const int b   = bh / H_;
    const int h   = bh % H_;
    const int w0  = blockIdx.x * 128;

    // prefetch tap 0 weights immediately
    issue_B(0, 0, smb, t);

    // ---- replicated bias tile -> init accumulators ----
    for (int idx = t; idx < 16 * 192; idx += 256) {
        int row = idx / 192, col = idx % 192;
        float bvv = (col < 64) ? bq[col] : (col < 128) ? bk[col - 64] : bv[col - 128];
        biasT[row * BIAS_LDM + col] = bvv;
    }
    __syncthreads();

    wmma::fragment<wmma::accumulator, 16, 16, 16, float> acc[2][6];
    #pragma unroll
    for (int i = 0; i < 2; i++)
        #pragma unroll
        for (int j = 0; j < 6; j++)
            wmma::load_matrix_sync(acc[i][j], biasT + warp_n * 96 + j * 16,
                                   BIAS_LDM, wmma::mem_row_major);

    #pragma unroll 1
    for (int tap = 0; tap < 9; tap++) {
        const int kh = tap / 3, kw = tap % 3;

        __syncthreads();   // prev tap's MMAs done (bias frag reads done at tap 0)

        if (kw == 0) {
            // ---- stage A window: 132 rows (w0-2 .. w0+129), hi/lo bf16 ----
            const int hh = h + (kh - 1) * 2;
            const bool hok = (hh >= 0) && (hh < H_);
            const float* xrow = X + ((size_t)(b * H_ + hh) * W_) * C_;
            for (int idx = t; idx < 132 * 16; idx += 256) {
                int r  = idx >> 4;
                int c4 = idx & 15;
                int ww = w0 + r - 2;
                float4 xv = make_float4(0.f, 0.f, 0.f, 0.f);
                if (hok && (unsigned)ww < (unsigned)W_)
                    xv = *reinterpret_cast<const float4*>(xrow + (size_t)ww * C_ + c4 * 4);
                __nv_bfloat162 h01 = __floats2bfloat162_rn(xv.x, xv.y);
                __nv_bfloat162 h23 = __floats2bfloat162_rn(xv.z, xv.w);
                __nv_bfloat162 l01 = __floats2bfloat162_rn(
                    xv.x - __bfloat162float(__low2bfloat16(h01)),
                    xv.y - __bfloat162float(__high2bfloat16(h01)));
                __nv_bfloat162 l23 = __floats2bfloat162_rn(
                    xv.z - __bfloat162float(__low2bfloat16(h23)),
                    xv.w - __bfloat162float(__high2bfloat16(h23)));
                uint2 hv, lv;
                hv.x = *reinterpret_cast<uint32_t*>(&h01);
                hv.y = *reinterpret_cast<uint32_t*>(&h23);
                lv.x = *reinterpret_cast<uint32_t*>(&l01);
                lv.y = *reinterpret_cast<uint32_t*>(&l23);
                *reinterpret_cast<uint2*>(A_hi + r * A_LDM + c4 * 4) = hv;
                *reinterpret_cast<uint2*>(A_lo + r * A_LDM + c4 * 4) = lv;
            }
        }

        // prefetch next tap's weights into the alternate buffer
        if (tap < 8) {
            issue_B(tap + 1, (tap + 1) & 1, smb, t);
            asm volatile("cp.async.wait_group 1;" ::: "memory");  // tap's group done
        } else {
            asm volatile("cp.async.wait_group 0;" ::: "memory");
        }
        __syncthreads();

        // ---- MMA: 4 k-steps x (2m x 6n) x 3 splits on buffer tap&1 ----
        __nv_bfloat16* B_hi = reinterpret_cast<__nv_bfloat16*>(sm + SM_BH(tap & 1));
        __nv_bfloat16* B_lo = reinterpret_cast<__nv_bfloat16*>(sm + SM_BL(tap & 1));
        const int rbase = warp_m * 32 + kw * 2;
        #pragma unroll
        for (int ks = 0; ks < 4; ks++) {
            const int c0 = ks * 16;
            wmma::fragment<wmma::matrix_a, 16, 16, 16, __nv_bfloat16, wmma::row_major> ah[2], al[2];
            #pragma unroll
            for (int i = 0; i < 2; i++) {
                wmma::load_matrix_sync(ah[i], A_hi + (rbase + i * 16) * A_LDM + c0, A_LDM);
                wmma::load_matrix_sync(al[i], A_lo + (rbase + i * 16) * A_LDM + c0, A_LDM);
            }
            #pragma unroll
            for (int j = 0; j < 6; j++) {
                wmma::fragment<wmma::matrix_b, 16, 16, 16, __nv_bfloat16, wmma::col_major> bhf, blf;
                const int n0 = warp_n * 96 + j * 16;
                wmma::load_matrix_sync(bhf, B_hi + n0 * B_LDM + c0, B_LDM);
                wmma::load_matrix_sync(blf, B_lo + n0 * B_LDM + c0, B_LDM);
                #pragma unroll
                for (int i = 0; i < 2; i++) {
                    wmma::mma_sync(acc[i][j], ah[i], bhf, acc[i][j]);
                    wmma::mma_sync(acc[i][j], ah[i], blf, acc[i][j]);
                    wmma::mma_sync(acc[i][j], al[i], bhf, acc[i][j]);
                }
            }
        }
    }

    // ---- epilogue: store fragments straight to g_q/g_k/g_v (fp32) ----
    #pragma unroll
    for (int i = 0; i < 2; i++) {
        const int m0 = warp_m * 32 + i * 16;
        const size_t pix0 = (size_t)bh * W_ + w0 + m0;
        #pragma unroll
        for (int j = 0; j < 6; j++) {
            const int n0 = warp_n * 96 + j * 16;
            float* dst = (n0 < 64) ? g_q : (n0 < 128) ? g_k : g_v;
            wmma::store_matrix_sync(dst + pix0 * 64 + (n0 & 63), acc[i][j],
                                    64, wmma::mem_row_major);
        }
    }
}

// ---------------------------------------------------------------------------
// Flash attention along W per (b,h). grid (W_/64, B_*H_), 256 threads.
// fp32 SIMT (known-good from round 2/4: ~465 us)
// ---------------------------------------------------------------------------
#define ATTN_SMEM ((64*68 + 64*68 + 64*64) * 4)

__global__ __launch_bounds__(256) void attn_kernel(float* __restrict__ out)
{
    extern __shared__ float smf[];
    float* Qs = smf;
    float* KP = smf + 64 * 68;
    float* Vs = smf + 2 * 64 * 68;

    const int t  = threadIdx.x;
    const int tq = t >> 4;
    const int tf = t & 15;
    const int bh = blockIdx.y;
    const int q0 = blockIdx.x * 64;

    const float* qb = g_q + (size_t)bh * W_ * F_;
    const float* kb = g_k + (size_t)bh * W_ * F_;
    const float* vb = g_v + (size_t)bh * W_ * F_;

    #pragma unroll
    for (int i = 0; i < 4; i++) {
        int idx = t + i * 256;
        int il  = idx >> 4;
        int c4  = idx & 15;
        float4 qv = *reinterpret_cast<const float4*>(qb + (size_t)(q0 + il) * F_ + c4 * 4);
        *reinterpret_cast<float4*>(Qs + il * 68 + c4 * 4) = qv;
    }

    float o[4][4];
    float m[4], l[4];
    #pragma unroll
    for (int i = 0; i < 4; i++) {
        m[i] = -INFINITY; l[i] = 0.f;
        #pragma unroll
        for (int j = 0; j < 4; j++) o[i][j] = 0.f;
    }
    __syncthreads();

    #pragma unroll 1
    for (int k0t = 0; k0t < W_; k0t += 64) {
        #pragma unroll
        for (int i = 0; i < 4; i++) {
            int idx = t + i * 256;
            int jl  = idx >> 4;
            int c4  = idx & 15;
            float4 kv = *reinterpret_cast<const float4*>(kb + (size_t)(k0t + jl) * F_ + c4 * 4);
            KP[(c4*4+0)*68 + jl] = kv.x;
            KP[(c4*4+1)*68 + jl] = kv.y;
            KP[(c4*4+2)*68 + jl] = kv.z;
            KP[(c4*4+3)*68 + jl] = kv.w;
            float4 vv = *reinterpret_cast<const float4*>(vb + (size_t)(k0t + jl) * F_ + c4 * 4);
            *reinterpret_cast<float4*>(Vs + jl * 64 + c4 * 4) = vv;
        }
        __syncthreads();

        float s[4][4];
        #pragma unroll
        for (int i = 0; i < 4; i++)
            #pragma unroll
            for (int j = 0; j < 4; j++) s[i][j] = 0.f;
        #pragma unroll 4
        for (int c0 = 0; c0 < 64; c0 += 4) {
            float4 q4[4];
            #pragma unroll
            for (int i = 0; i < 4; i++)
                q4[i] = *reinterpret_cast<const float4*>(Qs + (tq*4 + i) * 68 + c0);
            #pragma unroll
            for (int cc = 0; cc < 4; cc++) {
                float4 k4 = *reinterpret_cast<const float4*>(KP + (c0 + cc) * 68 + tf * 4);
                float kr[4] = {k4.x, k4.y, k4.z, k4.w};
                #pragma unroll
                for (int i = 0; i < 4; i++) {
                    float x = reinterpret_cast<const float*>(&q4[i])[cc];
                    #pragma unroll
                    for (int j = 0; j < 4; j++)
                        s[i][j] = fmaf(x, kr[j], s[i][j]);
                }
            }
        }

        float p[4][4];
        #pragma unroll
        for (int i = 0; i < 4; i++) {
            float mm = fmaxf(fmaxf(s[i][0], s[i][1]), fmaxf(s[i][2], s[i][3]));
            #pragma unroll
            for (int d = 1; d < 16; d <<= 1)
                mm = fmaxf(mm, __shfl_xor_sync(0xffffffffu, mm, d));
            float mnew = fmaxf(m[i], mm);
            float sc = __expf(m[i] - mnew);
            m[i] = mnew;
            float ls = 0.f;
            #pragma unroll
            for (int j = 0; j < 4; j++) {
                p[i][j] = __expf(s[i][j] - mnew);
                ls += p[i][j];
            }
            #pragma unroll
            for (int d = 1; d < 16; d <<= 1)
                ls += __shfl_xor_sync(0xffffffffu, ls, d);
            l[i] = l[i] * sc + ls;
            #pragma unroll
            for (int j = 0; j < 4; j++) o[i][j] *= sc;
        }

        __syncthreads();
        #pragma unroll
        for (int i = 0; i < 4; i++) {
            float4 pv = make_float4(p[i][0], p[i][1], p[i][2], p[i][3]);
            *reinterpret_cast<float4*>(KP + (tq*4 + i) * 68 + tf * 4) = pv;
        }
        __syncthreads();

        #pragma unroll 4
        for (int k0 = 0; k0 < 64; k0 += 4) {
            float4 p4[4];
            #pragma unroll
            for (int i = 0; i < 4; i++)
                p4[i] = *reinterpret_cast<const float4*>(KP + (tq*4 + i) * 68 + k0);
            #pragma unroll
            for (int kk = 0; kk < 4; kk++) {
                float4 v4 = *reinterpret_cast<const float4*>(Vs + (k0 + kk) * 64 + tf * 4);
                float vr[4] = {v4.x, v4.y, v4.z, v4.w};
                #pragma unroll
                for (int i = 0; i < 4; i++) {
                    float x = reinterpret_cast<const float*>(&p4[i])[kk];
                    #pragma unroll
                    for (int j = 0; j < 4; j++)
                        o[i][j] = fmaf(x, vr[j], o[i][j]);
                }
            }
        }
        __syncthreads();
    }

    #pragma unroll
    for (int i = 0; i < 4; i++) {
        float inv = 1.0f / l[i];
        size_t off = ((size_t)bh * W_ + q0 + tq * 4 + i) * F_ + tf * 4;
        float4 r;
        r.x = o[i][0] * inv; r.y = o[i][1] * inv;
        r.z = o[i][2] * inv; r.w = o[i][3] * inv;
        *reinterpret_cast<float4*>(out + off) = r;
    }
}

// ---------------------------------------------------------------------------
extern "C" void kernel_launch(void* const* d_in, const int* in_sizes, int n_in,
                              void* d_out, int out_size)
{
    const float* X  = (const float*)d_in[0];
    const float* Wq = (const float*)d_in[1];
    const float* bq = (const float*)d_in[2];
    const float* Wk = (const float*)d_in[3];
    const float* bk = (const float*)d_in[4];
    const float* Wv = (const float*)d_in[5];
    const float* bv = (const float*)d_in[6];
    float* out = (float*)d_out;

    cudaFuncSetAttribute(conv_qkv_wmma_kernel,
                         cudaFuncAttributeMaxDynamicSharedMemorySize, CONV_SMEM);
    cudaFuncSetAttribute(attn_kernel,
                         cudaFuncAttributeMaxDynamicSharedMemorySize, ATTN_SMEM);

    prep_w_kernel<<<(9 * 192 * 64 + 255) / 256, 256>>>(Wq, Wk, Wv);

    dim3 cgrid(W_ / 128, B_ * H_);
    conv_qkv_wmma_kernel<<<cgrid, 256, CONV_SMEM>>>(X, bq, bk, bv);

    dim3 agrid(W_ / 64, B_ * H_);
    attn_kernel<<<agrid, 256, ATTN_SMEM>>>(out);
}